// round 2
// baseline (speedup 1.0000x reference)
#include <cuda_runtime.h>

#define BATCH 4
#define NPTS  4096
#define KPN   512
#define KNN   32
#define NDIR  2

#define RT  512   // refs per slice (staged in smem)
#define QT  1024  // queries per block
#define TPB 256

// Scratch: per-(dir,batch,query) running min of (rn - 2*dot), encoded for atomicMin
__device__ unsigned g_minbits[NDIR * BATCH * NPTS];

// Order-preserving float->uint map (works for negatives too)
__device__ __forceinline__ unsigned enc_f(float f) {
    unsigned u = __float_as_uint(f);
    return (u & 0x80000000u) ? ~u : (u | 0x80000000u);
}
__device__ __forceinline__ float dec_f(unsigned e) {
    unsigned u = (e & 0x80000000u) ? (e & 0x7FFFFFFFu) : ~e;
    return __uint_as_float(u);
}

__device__ __forceinline__ float block_reduce_sum(float v) {
    __shared__ float sh[32];
    int lane = threadIdx.x & 31;
    int wid  = threadIdx.x >> 5;
    #pragma unroll
    for (int o = 16; o; o >>= 1) v += __shfl_down_sync(0xffffffffu, v, o);
    if (lane == 0) sh[wid] = v;
    __syncthreads();
    if (wid == 0) {
        v = (lane < (int)(blockDim.x >> 5)) ? sh[lane] : 0.0f;
        #pragma unroll
        for (int o = 16; o; o >>= 1) v += __shfl_down_sync(0xffffffffu, v, o);
    }
    return v;
}

// ---------------------------------------------------------------------------
// Kernel 1: init scratch mins to +inf (encoded) and zero the two outputs
// ---------------------------------------------------------------------------
__global__ void init_kernel(float* out) {
    int i = blockIdx.x * blockDim.x + threadIdx.x;
    if (i < NDIR * BATCH * NPTS) g_minbits[i] = 0xFF800000u;  // enc(+inf)
    if (i == 0) { out[0] = 0.0f; out[1] = 0.0f; }
}

// ---------------------------------------------------------------------------
// Kernel 2: tiled nearest-neighbor (squared) distance, both directions.
// grid = NDIR * BATCH * (NPTS/QT) * (NPTS/RT) = 2*4*4*8 = 256 blocks
// Each thread owns 4 query points; loop over RT refs staged in smem.
// Tracks min of (|r|^2 - 2 q.r); |q|^2 added in the finalize kernel.
// ---------------------------------------------------------------------------
__global__ void min_kernel(const float* __restrict__ src_tr,
                           const float* __restrict__ tgt) {
    __shared__ float sx[RT], sy[RT], sz[RT], sn[RT];

    int bid   = blockIdx.x;
    int rs    = bid & 7;         // ref slice 0..7
    int qb    = (bid >> 3) & 3;  // query block 0..3
    int b     = (bid >> 5) & 3;  // batch
    int dir   = bid >> 7;        // 0: queries=preds(src_tr), refs=gts(tgt); 1: swapped

    const float* Q  = (dir ? tgt : src_tr) + b * 3 * NPTS;
    const float* Rf = (dir ? src_tr : tgt) + b * 3 * NPTS;

    int tid = threadIdx.x;
    for (int t = tid; t < RT; t += TPB) {
        int r = rs * RT + t;
        float rx = Rf[r];
        float ry = Rf[NPTS + r];
        float rz = Rf[2 * NPTS + r];
        sx[t] = rx; sy[t] = ry; sz[t] = rz;
        sn[t] = rx * rx + ry * ry + rz * rz;
    }
    __syncthreads();

    float qx[4], qy[4], qz[4], m[4];
    int q0 = qb * QT;
    #pragma unroll
    for (int u = 0; u < 4; u++) {
        int q = q0 + u * TPB + tid;
        qx[u] = Q[q];
        qy[u] = Q[NPTS + q];
        qz[u] = Q[2 * NPTS + q];
        m[u]  = 3.4e38f;
    }

    #pragma unroll 4
    for (int r = 0; r < RT; r++) {
        float rx = sx[r], ry = sy[r], rz = sz[r], rn = sn[r];
        #pragma unroll
        for (int u = 0; u < 4; u++) {
            float s = fmaf(qx[u], rx, fmaf(qy[u], ry, qz[u] * rz));
            float t = fmaf(-2.0f, s, rn);
            m[u] = fminf(m[u], t);
        }
    }

    unsigned* gm = g_minbits + (dir * BATCH + b) * NPTS;
    #pragma unroll
    for (int u = 0; u < 4; u++) {
        int q = q0 + u * TPB + tid;
        atomicMin(&gm[q], enc_f(m[u]));
    }
}

// ---------------------------------------------------------------------------
// Kernel 3: finalize gal: d = |q|^2 + min, huber, sum -> out[1]
// grid = 32768/256 = 128 blocks
// ---------------------------------------------------------------------------
__global__ void gal_kernel(const float* __restrict__ src_tr,
                           const float* __restrict__ tgt,
                           float* out) {
    int i = blockIdx.x * blockDim.x + threadIdx.x;  // 0..32767
    int q   = i & (NPTS - 1);
    int b   = (i >> 12) & 3;
    int dir = i >> 14;
    const float* Q = (dir ? tgt : src_tr) + b * 3 * NPTS;
    float qx = Q[q], qy = Q[NPTS + q], qz = Q[2 * NPTS + q];
    float qn = qx * qx + qy * qy + qz * qz;
    float d  = qn + dec_f(g_minbits[i]);

    const float c = 0.01f;
    float h = (d < c) ? (0.5f * d * d) : fmaf(c, d, -0.5f * c * c);

    float s = block_reduce_sum(h);
    if (threadIdx.x == 0) atomicAdd(&out[1], s);
}

// ---------------------------------------------------------------------------
// Kernel 4: neighborhood consensus loss -> out[0]
//   knn: sum((sknn-tknn)^2)/KNN over 196608 elems
//   keypoints: sum((R p + t - tk)^2) over B*KP points (threads with i < 2048)
// grid = 256 blocks x 256 threads, strided
// ---------------------------------------------------------------------------
__global__ void nbh_kernel(const float* __restrict__ sk,
                           const float* __restrict__ tk,
                           const float* __restrict__ Rot,
                           const float* __restrict__ Tr,
                           const float* __restrict__ sknn,
                           const float* __restrict__ tknn,
                           float* out) {
    int i = blockIdx.x * blockDim.x + threadIdx.x;
    int stride = gridDim.x * blockDim.x;
    const int TOT = BATCH * 3 * KPN * KNN;  // 196608

    float acc = 0.0f;
    for (int j = i; j < TOT; j += stride) {
        float d = sknn[j] - tknn[j];
        acc = fmaf(d, d, acc);
    }
    acc *= (1.0f / (float)KNN);

    if (i < BATCH * KPN) {
        int b = i / KPN;
        int p = i - b * KPN;
        const float* Rb = Rot + b * 9;
        const float* tb = Tr + b * 3;
        const float* skb = sk + b * 3 * KPN;
        const float* tkb = tk + b * 3 * KPN;
        float px = skb[p], py = skb[KPN + p], pz = skb[2 * KPN + p];
        #pragma unroll
        for (int cdim = 0; cdim < 3; cdim++) {
            float v = fmaf(Rb[cdim * 3 + 0], px,
                      fmaf(Rb[cdim * 3 + 1], py,
                      fmaf(Rb[cdim * 3 + 2], pz, tb[cdim])))
                      - tkb[cdim * KPN + p];
            acc = fmaf(v, v, acc);
        }
    }

    float s = block_reduce_sum(acc);
    if (threadIdx.x == 0) atomicAdd(&out[0], s);
}

// ---------------------------------------------------------------------------
extern "C" void kernel_launch(void* const* d_in, const int* in_sizes, int n_in,
                              void* d_out, int out_size) {
    const float* src_kp   = (const float*)d_in[0];  // (B,3,KP)
    const float* tgt_kp   = (const float*)d_in[1];  // (B,3,KP)
    const float* rot      = (const float*)d_in[2];  // (B,3,3)
    const float* tra      = (const float*)d_in[3];  // (B,3)
    const float* src_knn  = (const float*)d_in[4];  // (B,3,KP,K)
    const float* tgt_knn  = (const float*)d_in[5];  // (B,3,KP,K)
    // d_in[6] = k (constant 32, hardcoded)
    const float* src_tr   = (const float*)d_in[7];  // (B,3,N)
    const float* tgt      = (const float*)d_in[8];  // (B,3,N)
    float* out = (float*)d_out;                     // out[0]=nbh, out[1]=gal

    init_kernel<<<(NDIR * BATCH * NPTS + 255) / 256, 256>>>(out);
    min_kernel<<<NDIR * BATCH * (NPTS / QT) * (NPTS / RT), TPB>>>(src_tr, tgt);
    gal_kernel<<<(NDIR * BATCH * NPTS) / 256, 256>>>(src_tr, tgt, out);
    nbh_kernel<<<256, 256>>>(src_kp, tgt_kp, rot, tra, src_knn, tgt_knn, out);
}

// round 3
// speedup vs baseline: 1.5814x; 1.5814x over previous
#include <cuda_runtime.h>

#define BATCH 4
#define NPTS  4096
#define KPN   512
#define KNN   32
#define NDIR  2

#define RS   32            // ref slices per (dir,batch)
#define RT   (NPTS / RS)   // 128 refs per slice == TPB
#define TPB  128
#define QPT  8             // queries per thread (4 packed pairs)
#define QT   (TPB * QPT)   // 1024 queries per block
#define QB   (NPTS / QT)   // 4 query blocks per (dir,batch)

// Per-(dir,batch,slice,query) partial min of (|r|^2 - 2 q.r). 4 MB scratch.
__device__ float g_part[NDIR * BATCH * RS * NPTS];

// Packed f32x2 FMA (sm_103a FFMA2 — only reachable via PTX)
__device__ __forceinline__ float2 ffma2(float2 a, float2 b, float2 c) {
    float2 d;
    asm("fma.rn.f32x2 %0, %1, %2, %3;"
        : "=l"(*reinterpret_cast<unsigned long long*>(&d))
        : "l"(*reinterpret_cast<const unsigned long long*>(&a)),
          "l"(*reinterpret_cast<const unsigned long long*>(&b)),
          "l"(*reinterpret_cast<const unsigned long long*>(&c)));
    return d;
}

// ---------------------------------------------------------------------------
// Kernel 1: tiled NN distance partial-min, both directions.
// grid = NDIR*BATCH*QB*RS = 1024 blocks x 128 threads.
// Each thread owns 8 queries (4 f32x2 pairs), loops over RT refs in smem.
// Inner iter: 4 LDS.64 + 12 FFMA2 + 8 FMNMX = 24 issues for 8 distances.
// ---------------------------------------------------------------------------
__global__ void __launch_bounds__(TPB) min_kernel(const float* __restrict__ src_tr,
                                                  const float* __restrict__ tgt,
                                                  float* __restrict__ out) {
    __shared__ float2 srx[RT], sry[RT], srz[RT], srn[RT];

    int bid = blockIdx.x;
    int rs  = bid & (RS - 1);        // 0..31
    int qb  = (bid >> 5) & (QB - 1); // 0..3
    int b   = (bid >> 7) & 3;        // batch
    int dir = bid >> 9;              // 0: queries=preds(src_tr) refs=gts(tgt); 1: swapped

    int tid = threadIdx.x;
    if (bid == 0 && tid == 0) { out[0] = 0.0f; out[1] = 0.0f; }

    const float* Q  = (dir ? tgt : src_tr) + b * 3 * NPTS;
    const float* Rf = (dir ? src_tr : tgt) + b * 3 * NPTS;

    // Stage one ref per thread, duplicated into both f32x2 lanes.
    {
        int r = rs * RT + tid;
        float rx = Rf[r];
        float ry = Rf[NPTS + r];
        float rz = Rf[2 * NPTS + r];
        float rn = fmaf(rx, rx, fmaf(ry, ry, rz * rz));
        srx[tid] = make_float2(rx, rx);
        sry[tid] = make_float2(ry, ry);
        srz[tid] = make_float2(rz, rz);
        srn[tid] = make_float2(rn, rn);
    }
    __syncthreads();

    // Load 8 queries as 4 pairs, pre-scaled by -2.
    float2 qx[4], qy[4], qz[4];
    float  m[8];
    int q0 = qb * QT + tid;
    #pragma unroll
    for (int j = 0; j < 4; j++) {
        int qa = q0 + (2 * j) * TPB;
        int qc = q0 + (2 * j + 1) * TPB;
        qx[j] = make_float2(-2.0f * Q[qa],            -2.0f * Q[qc]);
        qy[j] = make_float2(-2.0f * Q[NPTS + qa],     -2.0f * Q[NPTS + qc]);
        qz[j] = make_float2(-2.0f * Q[2 * NPTS + qa], -2.0f * Q[2 * NPTS + qc]);
        m[2 * j] = 3.4e38f; m[2 * j + 1] = 3.4e38f;
    }

    #pragma unroll 4
    for (int r = 0; r < RT; r++) {
        float2 rx = srx[r], ry = sry[r], rz = srz[r], rn = srn[r];
        #pragma unroll
        for (int j = 0; j < 4; j++) {
            float2 t = ffma2(qx[j], rx, ffma2(qy[j], ry, ffma2(qz[j], rz, rn)));
            m[2 * j]     = fminf(m[2 * j],     t.x);
            m[2 * j + 1] = fminf(m[2 * j + 1], t.y);
        }
    }

    float* P = g_part + ((dir * BATCH + b) * RS + rs) * NPTS;
    #pragma unroll
    for (int j = 0; j < 4; j++) {
        P[q0 + (2 * j) * TPB]     = m[2 * j];
        P[q0 + (2 * j + 1) * TPB] = m[2 * j + 1];
    }
}

// ---------------------------------------------------------------------------
// Dual block reduce: sums both components of a float2.
// ---------------------------------------------------------------------------
__device__ __forceinline__ float2 block_reduce2(float2 v) {
    __shared__ float2 sh[32];
    int lane = threadIdx.x & 31;
    int wid  = threadIdx.x >> 5;
    #pragma unroll
    for (int o = 16; o; o >>= 1) {
        v.x += __shfl_down_sync(0xffffffffu, v.x, o);
        v.y += __shfl_down_sync(0xffffffffu, v.y, o);
    }
    if (lane == 0) sh[wid] = v;
    __syncthreads();
    if (wid == 0) {
        v = (lane < (int)(blockDim.x >> 5)) ? sh[lane] : make_float2(0.0f, 0.0f);
        #pragma unroll
        for (int o = 16; o; o >>= 1) {
            v.x += __shfl_down_sync(0xffffffffu, v.x, o);
            v.y += __shfl_down_sync(0xffffffffu, v.y, o);
        }
    }
    return v;
}

// ---------------------------------------------------------------------------
// Kernel 2: fused finalize.
//   gal: d = |q|^2 + min over RS partials, huber, sum -> out[1]
//   nbh: knn L2 (float4) / K + keypoint transform loss -> out[0]
// grid = 128 blocks x 256 threads = 32768 threads (one per (dir,b,q)).
// ---------------------------------------------------------------------------
__global__ void __launch_bounds__(256) fin_kernel(const float* __restrict__ src_tr,
                                                  const float* __restrict__ tgt,
                                                  const float* __restrict__ sk,
                                                  const float* __restrict__ tk,
                                                  const float* __restrict__ Rot,
                                                  const float* __restrict__ Tr,
                                                  const float* __restrict__ sknn,
                                                  const float* __restrict__ tknn,
                                                  float* __restrict__ out) {
    int i   = blockIdx.x * blockDim.x + threadIdx.x;  // 0..32767
    int q   = i & (NPTS - 1);
    int b   = (i >> 12) & 3;
    int dir = i >> 14;

    // --- gal term ---
    const float* Q = (dir ? tgt : src_tr) + b * 3 * NPTS;
    float qx = Q[q], qy = Q[NPTS + q], qz = Q[2 * NPTS + q];
    float qn = fmaf(qx, qx, fmaf(qy, qy, qz * qz));

    const float* P = g_part + (dir * BATCH + b) * RS * NPTS + q;
    float v = 3.4e38f;
    #pragma unroll
    for (int s = 0; s < RS; s++) v = fminf(v, P[s * NPTS]);

    float d = qn + v;
    const float c = 0.01f;
    float h = (d < c) ? (0.5f * d * d) : fmaf(c, d, -0.5f * c * c);

    // --- knn consensus (vectorized) ---
    const int TOT4 = BATCH * 3 * KPN * KNN / 4;  // 49152
    const float4* s4 = (const float4*)sknn;
    const float4* t4 = (const float4*)tknn;
    float acc = 0.0f;
    int nthr = gridDim.x * blockDim.x;  // 32768
    for (int j = i; j < TOT4; j += nthr) {
        float4 a = s4[j], bb = t4[j];
        float d0 = a.x - bb.x, d1 = a.y - bb.y, d2 = a.z - bb.z, d3 = a.w - bb.w;
        acc = fmaf(d0, d0, fmaf(d1, d1, fmaf(d2, d2, fmaf(d3, d3, acc))));
    }
    acc *= (1.0f / (float)KNN);

    // --- keypoint transform loss ---
    if (i < BATCH * KPN) {
        int kb = i >> 9;          // i / KPN
        int p  = i & (KPN - 1);
        const float* Rb  = Rot + kb * 9;
        const float* tb  = Tr + kb * 3;
        const float* skb = sk + kb * 3 * KPN;
        const float* tkb = tk + kb * 3 * KPN;
        float px = skb[p], py = skb[KPN + p], pz = skb[2 * KPN + p];
        #pragma unroll
        for (int cd = 0; cd < 3; cd++) {
            float w = fmaf(Rb[cd * 3 + 0], px,
                      fmaf(Rb[cd * 3 + 1], py,
                      fmaf(Rb[cd * 3 + 2], pz, tb[cd])))
                      - tkb[cd * KPN + p];
            acc = fmaf(w, w, acc);
        }
    }

    float2 sums = block_reduce2(make_float2(acc, h));
    if (threadIdx.x == 0) {
        atomicAdd(&out[0], sums.x);
        atomicAdd(&out[1], sums.y);
    }
}

// ---------------------------------------------------------------------------
extern "C" void kernel_launch(void* const* d_in, const int* in_sizes, int n_in,
                              void* d_out, int out_size) {
    const float* src_kp  = (const float*)d_in[0];  // (B,3,KP)
    const float* tgt_kp  = (const float*)d_in[1];  // (B,3,KP)
    const float* rot     = (const float*)d_in[2];  // (B,3,3)
    const float* tra     = (const float*)d_in[3];  // (B,3)
    const float* src_knn = (const float*)d_in[4];  // (B,3,KP,K)
    const float* tgt_knn = (const float*)d_in[5];  // (B,3,KP,K)
    // d_in[6] = k (constant 32, hardcoded)
    const float* src_tr  = (const float*)d_in[7];  // (B,3,N)
    const float* tgt     = (const float*)d_in[8];  // (B,3,N)
    float* out = (float*)d_out;                    // out[0]=nbh, out[1]=gal

    min_kernel<<<NDIR * BATCH * QB * RS, TPB>>>(src_tr, tgt, out);
    fin_kernel<<<(NDIR * BATCH * NPTS) / 256, 256>>>(src_tr, tgt, src_kp, tgt_kp,
                                                     rot, tra, src_knn, tgt_knn, out);
}

// round 4
// speedup vs baseline: 1.5888x; 1.0047x over previous
#include <cuda_runtime.h>

#define BATCH 4
#define NPTS  4096
#define KPN   512
#define KNN   32

#define TPB   128
#define BSL   128            // B (ref) slice per block, staged in smem
#define ATILE 1024           // A (query) tile per block (8 per thread)
#define NAT   (NPTS / ATILE) // 4
#define NBS   (NPTS / BSL)   // 32
#define INF   3.4e38f

// Full-distance partial mins.
__device__ float g_rowpart[BATCH * NBS * NPTS];  // 2 MB: per (b, Bslice, A-point)
__device__ float g_colpart[BATCH * NAT * NPTS];  // 256 KB: per (b, Atile, B-point)

// Packed f32x2 ops (sm_103a, PTX-only)
__device__ __forceinline__ float2 ffma2(float2 a, float2 b, float2 c) {
    float2 d;
    asm("fma.rn.f32x2 %0, %1, %2, %3;"
        : "=l"(*reinterpret_cast<unsigned long long*>(&d))
        : "l"(*reinterpret_cast<const unsigned long long*>(&a)),
          "l"(*reinterpret_cast<const unsigned long long*>(&b)),
          "l"(*reinterpret_cast<const unsigned long long*>(&c)));
    return d;
}
__device__ __forceinline__ float2 fadd2(float2 a, float2 b) {
    float2 d;
    asm("add.rn.f32x2 %0, %1, %2;"
        : "=l"(*reinterpret_cast<unsigned long long*>(&d))
        : "l"(*reinterpret_cast<const unsigned long long*>(&a)),
          "l"(*reinterpret_cast<const unsigned long long*>(&b)));
    return d;
}

// ---------------------------------------------------------------------------
// Kernel 1: fused tile pass. Each block: A-tile (1024 queries, 8/thread in
// regs) x B-slice (128 refs in smem). Computes FULL squared distances ONCE,
// extracting row partial mins (regs) AND col partial mins (per-warp smem,
// skewed ref index -> no conflicts, no cross-warp races).
// grid = BATCH * NAT * NBS = 512 blocks x 128 threads.
// ---------------------------------------------------------------------------
__global__ void __launch_bounds__(TPB) min_kernel(const float* __restrict__ A,
                                                  const float* __restrict__ B,
                                                  float* __restrict__ out) {
    __shared__ float4 sB1[BSL];        // (bx,bx,by,by)
    __shared__ float4 sB2[BSL];        // (bz,bz,bn,bn)
    __shared__ float  cmin[4][BSL];    // per-warp col partial mins

    int bid = blockIdx.x;
    int bs  = bid & (NBS - 1);         // B slice 0..31
    int at  = (bid >> 5) & (NAT - 1);  // A tile 0..3
    int b   = bid >> 7;                // batch

    int t = threadIdx.x;
    int w = t >> 5;
    if (bid == 0 && t == 0) { out[0] = 0.0f; out[1] = 0.0f; }

    const float* Ab = A + b * 3 * NPTS;  // gts (tgt)
    const float* Bb = B + b * 3 * NPTS;  // preds (src_transformed)

    // Stage B slice (duplicated lanes for packed math) + init col accumulators
    {
        int j = bs * BSL + t;
        float bx = Bb[j], by = Bb[NPTS + j], bz = Bb[2 * NPTS + j];
        float bn = fmaf(bx, bx, fmaf(by, by, bz * bz));
        sB1[t] = make_float4(bx, bx, by, by);
        sB2[t] = make_float4(bz, bz, bn, bn);
        cmin[0][t] = INF; cmin[1][t] = INF; cmin[2][t] = INF; cmin[3][t] = INF;
    }
    __syncthreads();

    // 8 queries per thread as 4 packed pairs; x/y/z pre-scaled by -2, norm kept.
    float2 qx[4], qy[4], qz[4], qn[4];
    float  m[8];
    int i0 = at * ATILE + t;
    #pragma unroll
    for (int jp = 0; jp < 4; jp++) {
        int ia = i0 + (2 * jp) * TPB;
        int ic = i0 + (2 * jp + 1) * TPB;
        float ax = Ab[ia], ay = Ab[NPTS + ia], az = Ab[2 * NPTS + ia];
        float cx = Ab[ic], cy = Ab[NPTS + ic], cz = Ab[2 * NPTS + ic];
        float na = fmaf(ax, ax, fmaf(ay, ay, az * az));
        float nc = fmaf(cx, cx, fmaf(cy, cy, cz * cz));
        qx[jp] = make_float2(-2.0f * ax, -2.0f * cx);
        qy[jp] = make_float2(-2.0f * ay, -2.0f * cy);
        qz[jp] = make_float2(-2.0f * az, -2.0f * cz);
        qn[jp] = make_float2(na, nc);
        m[2 * jp] = INF; m[2 * jp + 1] = INF;
    }

    #pragma unroll 2
    for (int i = 0; i < BSL; i++) {
        int r = (t + i) & (BSL - 1);   // skewed: warp lanes hit distinct refs
        float4 b1 = sB1[r];
        float4 b2 = sB2[r];
        float2 rx = make_float2(b1.x, b1.y);
        float2 ry = make_float2(b1.z, b1.w);
        float2 rz = make_float2(b2.x, b2.y);
        float2 rn = make_float2(b2.z, b2.w);

        float p[4];
        #pragma unroll
        for (int jp = 0; jp < 4; jp++) {
            float2 bias = fadd2(qn[jp], rn);  // qn + rn (full-dist bias)
            float2 d2 = ffma2(qx[jp], rx, ffma2(qy[jp], ry, ffma2(qz[jp], rz, bias)));
            m[2 * jp]     = fminf(m[2 * jp],     d2.x);
            m[2 * jp + 1] = fminf(m[2 * jp + 1], d2.y);
            p[jp] = fminf(d2.x, d2.y);
        }
        float v = fminf(fminf(p[0], p[1]), fminf(p[2], p[3]));
        cmin[w][r] = fminf(cmin[w][r], v);
    }
    __syncthreads();

    // Row partials (full dists): per A-point min over this B slice.
    float* RP = g_rowpart + (b * NBS + bs) * NPTS + i0;
    #pragma unroll
    for (int u = 0; u < 8; u++) RP[u * TPB] = m[u];

    // Col partials: merge 4 warp arrays, write per B-point min over this A tile.
    float cv = fminf(fminf(cmin[0][t], cmin[1][t]), fminf(cmin[2][t], cmin[3][t]));
    g_colpart[(b * NAT + at) * NPTS + bs * BSL + t] = cv;
}

// ---------------------------------------------------------------------------
__device__ __forceinline__ float2 block_reduce2(float2 v) {
    __shared__ float2 sh[32];
    int lane = threadIdx.x & 31;
    int wid  = threadIdx.x >> 5;
    #pragma unroll
    for (int o = 16; o; o >>= 1) {
        v.x += __shfl_down_sync(0xffffffffu, v.x, o);
        v.y += __shfl_down_sync(0xffffffffu, v.y, o);
    }
    if (lane == 0) sh[wid] = v;
    __syncthreads();
    if (wid == 0) {
        v = (lane < (int)(blockDim.x >> 5)) ? sh[lane] : make_float2(0.0f, 0.0f);
        #pragma unroll
        for (int o = 16; o; o >>= 1) {
            v.x += __shfl_down_sync(0xffffffffu, v.x, o);
            v.y += __shfl_down_sync(0xffffffffu, v.y, o);
        }
    }
    return v;
}

// ---------------------------------------------------------------------------
// Kernel 2: finalize. Partials are FULL distances -> just min-reduce + huber.
//   dir0 threads: rowmin over 32 partials; dir1 threads: colmin over 4.
//   Plus knn L2 (float4) / K and keypoint transform loss.
// grid = 128 blocks x 256 threads = 32768 (one per (dir,b,point)).
// ---------------------------------------------------------------------------
__global__ void __launch_bounds__(256) fin_kernel(const float* __restrict__ sk,
                                                  const float* __restrict__ tk,
                                                  const float* __restrict__ Rot,
                                                  const float* __restrict__ Tr,
                                                  const float* __restrict__ sknn,
                                                  const float* __restrict__ tknn,
                                                  float* __restrict__ out) {
    int i   = blockIdx.x * blockDim.x + threadIdx.x;  // 0..32767
    int q   = i & (NPTS - 1);
    int b   = (i >> 12) & 3;
    int dir = i >> 14;                                 // warp-uniform

    float d = INF;
    if (dir == 0) {
        const float* P = g_rowpart + b * NBS * NPTS + q;
        #pragma unroll
        for (int s = 0; s < NBS; s++) d = fminf(d, P[s * NPTS]);
    } else {
        const float* P = g_colpart + b * NAT * NPTS + q;
        #pragma unroll
        for (int s = 0; s < NAT; s++) d = fminf(d, P[s * NPTS]);
    }
    const float c = 0.01f;
    float h = (d < c) ? (0.5f * d * d) : fmaf(c, d, -0.5f * c * c);

    // knn consensus (float4-vectorized)
    const int TOT4 = BATCH * 3 * KPN * KNN / 4;  // 49152
    const float4* s4 = (const float4*)sknn;
    const float4* t4 = (const float4*)tknn;
    float acc = 0.0f;
    int nthr = gridDim.x * blockDim.x;  // 32768
    for (int j = i; j < TOT4; j += nthr) {
        float4 a = s4[j], bb = t4[j];
        float d0 = a.x - bb.x, d1 = a.y - bb.y, d2 = a.z - bb.z, d3 = a.w - bb.w;
        acc = fmaf(d0, d0, fmaf(d1, d1, fmaf(d2, d2, fmaf(d3, d3, acc))));
    }
    acc *= (1.0f / (float)KNN);

    // keypoint transform loss
    if (i < BATCH * KPN) {
        int kb = i >> 9;
        int p  = i & (KPN - 1);
        const float* Rb  = Rot + kb * 9;
        const float* tb  = Tr + kb * 3;
        const float* skb = sk + kb * 3 * KPN;
        const float* tkb = tk + kb * 3 * KPN;
        float px = skb[p], py = skb[KPN + p], pz = skb[2 * KPN + p];
        #pragma unroll
        for (int cd = 0; cd < 3; cd++) {
            float wv = fmaf(Rb[cd * 3 + 0], px,
                       fmaf(Rb[cd * 3 + 1], py,
                       fmaf(Rb[cd * 3 + 2], pz, tb[cd])))
                       - tkb[cd * KPN + p];
            acc = fmaf(wv, wv, acc);
        }
    }

    float2 sums = block_reduce2(make_float2(acc, h));
    if (threadIdx.x == 0) {
        atomicAdd(&out[0], sums.x);
        atomicAdd(&out[1], sums.y);
    }
}

// ---------------------------------------------------------------------------
extern "C" void kernel_launch(void* const* d_in, const int* in_sizes, int n_in,
                              void* d_out, int out_size) {
    const float* src_kp  = (const float*)d_in[0];  // (B,3,KP)
    const float* tgt_kp  = (const float*)d_in[1];  // (B,3,KP)
    const float* rot     = (const float*)d_in[2];  // (B,3,3)
    const float* tra     = (const float*)d_in[3];  // (B,3)
    const float* src_knn = (const float*)d_in[4];  // (B,3,KP,K)
    const float* tgt_knn = (const float*)d_in[5];  // (B,3,KP,K)
    // d_in[6] = k (constant 32, hardcoded)
    const float* src_tr  = (const float*)d_in[7];  // (B,3,N) preds
    const float* tgt     = (const float*)d_in[8];  // (B,3,N) gts
    float* out = (float*)d_out;                    // out[0]=nbh, out[1]=gal

    // A = gts (tgt), B = preds (src_transformed); row+col mins cover both dirs.
    min_kernel<<<BATCH * NAT * NBS, TPB>>>(tgt, src_tr, out);
    fin_kernel<<<(2 * BATCH * NPTS) / 256, 256>>>(src_kp, tgt_kp, rot, tra,
                                                  src_knn, tgt_knn, out);
}